// round 14
// baseline (speedup 1.0000x reference)
#include <cuda_runtime.h>

// Problem dims (fixed by the reference)
#define Bn  4
#define Qn  256
#define KVn 1024
#define Hn  128
#define VSn 256

// Scratch (no cudaMalloc allowed)
__device__ float g_Eq[Bn * Qn * Hn];    // e^{2*clamp(q_proj)}
__device__ float g_Ek[Bn * KVn * Hn];   // e^{2*clamp(k_proj)}

// 2*log2(e): e^{2x} = 2^{x * 2*log2(e)}
#define TWO_LOG2E 2.885390081777927f

__device__ __forceinline__ void prefetch_l1(const void* p) {
    asm volatile("prefetch.global.L1 [%0];" :: "l"(p));
}

// ---------------------------------------------------------------------------
// Kernel 1: project rows, emit E = exp2(clamp(proj, +-40) * 2*log2(e)).
// 512 threads: thread = (4 output cols, 1 row, K-half). Split-K halves the
// FMA chain; halves combined via smem. W loaded as float4 (LDG.128).
// Key rows >= valid_len are skipped entirely (never read downstream).
// ---------------------------------------------------------------------------
__global__ __launch_bounds__(512)
void proj_kernel(const float* __restrict__ queries,
                 const float* __restrict__ keys,
                 const float* __restrict__ Wq,
                 const float* __restrict__ Wk,
                 const int* __restrict__ valid_lens) {
    const int r0 = blockIdx.x * 8;
    const float* in;
    const float* W;
    float* outp;
    if (r0 < Bn * Qn) {
        in   = queries + r0 * Hn;
        W    = Wq;
        outp = g_Eq + r0 * Hn;
    } else {
        const int rr = r0 - Bn * Qn;          // global key row
        const int b  = rr >> 10;              // / KVn
        const int j0 = rr & (KVn - 1);
        if (j0 >= valid_lens[b]) return;      // these Ek rows are never read
        in   = keys + rr * Hn;
        W    = Wk;
        outp = g_Ek + rr * Hn;
    }
    __shared__ float s[8][Hn];        // input rows
    __shared__ float part[8][Hn];     // K-half-1 partials

    const int t = threadIdx.x;
    #pragma unroll
    for (int u = 0; u < 2; u++) {
        const int idx = t + u * 512;
        s[idx >> 7][idx & 127] = in[idx];
    }
    __syncthreads();

    const int c4  = (t & 31) << 2;    // output column group (4 cols)
    const int row = (t >> 5) & 7;     // output row
    const int kh  = t >> 8;           // K half (0 or 1)

    const float* Wp   = W + kh * 64 * Hn + c4;
    const float* srow = &s[row][kh * 64];

    float ax = 0.f, ay = 0.f, az = 0.f, aw = 0.f;
    #pragma unroll 8
    for (int kk = 0; kk < 64; kk++) {
        const float  x = srow[kk];                       // warp-broadcast LDS
        const float4 w = *reinterpret_cast<const float4*>(Wp + kk * Hn);
        ax = fmaf(x, w.x, ax);
        ay = fmaf(x, w.y, ay);
        az = fmaf(x, w.z, az);
        aw = fmaf(x, w.w, aw);
    }

    if (kh == 1)
        *reinterpret_cast<float4*>(&part[row][c4]) = make_float4(ax, ay, az, aw);
    __syncthreads();
    if (kh == 0) {
        const float4 p = *reinterpret_cast<const float4*>(&part[row][c4]);
        float v[4] = {ax + p.x, ay + p.y, az + p.z, aw + p.w};
        float e[4];
        #pragma unroll
        for (int i = 0; i < 4; i++) {
            const float pc = fminf(fmaxf(v[i], -40.f), 40.f) * TWO_LOG2E;
            asm("ex2.approx.f32 %0, %1;" : "=f"(e[i]) : "f"(pc));
        }
        *reinterpret_cast<float4*>(&outp[row * Hn + c4]) =
            make_float4(e[0], e[1], e[2], e[3]);
    }
}

// ---------------------------------------------------------------------------
// Kernel 2 (fused): one block per query PAIR. 256 threads, 4 blocks/SM.
// Batch map b = (pair + (pair>>2)) & 3: bijective; blocks sharing an SM
// (bid stride 148 ≡ 0 mod 4 -> delta(b) ≡ 1 mod 4) cycle through batches.
//
// Pass 1 (scores): 16-lane-per-key, 2 keys/warp, both queries per key load.
//   L1 prefetch 2 iterations (32 keys) ahead: zero register cost, converts
//   the exposed L2 latency (~250-600 cyc) in the per-iteration dependent
//   chain into L1 hits (~39 cyc).
//   tanh(x) = 1 - 2/(Eq*Ek + 1); Sum_h w_h hoisted into accumulator init.
//   MUFU halved by pairing: w0/d0 + w1/d1 = (w0*d1c + w1*d0c)*rcp(d0c*d1c),
//   d clamped at 1e18 (true term < 3e-18 there -> clamp exact-enough, all
//   products finite -> no inf*0).
// Pass 2: per-row block softmax, race-free (separate max/sum scratch),
//   matching the -1e6 masking semantics; valid_len==0 -> uniform over all KV.
// Pass 3: AV with LDG.128 + prefetch 32 rows ahead; partials via smem.
// ---------------------------------------------------------------------------
__global__ __launch_bounds__(256, 4)
void attn_kernel(const float* __restrict__ values,
                 const int* __restrict__ valid_lens,
                 const float* __restrict__ wv,
                 float* __restrict__ out) {
    const int pair = blockIdx.x;                 // [0, 512)
    const int qp   = pair >> 2;                  // [0, 128)
    const int b    = (pair + qp) & 3;            // SM-cycling batch mix
    const int row0 = (b << 8) + (qp << 1);
    const int row1 = row0 + 1;
    const int tid  = threadIdx.x;
    const int lane = tid & 31;
    const int warp = tid >> 5;

    __shared__ float s_sc[2][KVn];
    __shared__ float s_av[2][4][VSn];
    __shared__ float s_rmax[2][8];
    __shared__ float s_rsum[2][8];

    const int L     = valid_lens[b];
    const bool uni  = (L <= 0);
    const int effL  = uni ? KVn : L;

    float Z0, Z1;
    if (!uni) {
        // ---- Pass 1: scores for both query rows ----
        const int sub = lane >> 4;          // which key of the duo (0..1)
        const int hb  = (lane & 15) << 3;   // h-chunk base (8 floats)

        float4 qa[2], qb[2], w2[2];
        float wsum_l = 0.f;
        #pragma unroll
        for (int i = 0; i < 2; i++) {
            qa[i] = *reinterpret_cast<const float4*>(&g_Eq[row0 * Hn + hb + i * 4]);
            qb[i] = *reinterpret_cast<const float4*>(&g_Eq[row1 * Hn + hb + i * 4]);
            float4 w = *reinterpret_cast<const float4*>(&wv[hb + i * 4]);
            wsum_l += ((w.x + w.y) + (w.z + w.w));
            w2[i] = make_float4(-2.f * w.x, -2.f * w.y, -2.f * w.z, -2.f * w.w);
        }
        const float* kbp = g_Ek + b * KVn * Hn;

        for (int j0 = warp * 2; j0 < effL; j0 += 16) {
            const int key = j0 + sub;
            const int kc  = (key < effL) ? key : (effL - 1);   // safe load
            // prefetch 2 iterations ahead (clamped -> always in-bounds)
            const int kpf = (key + 32 < effL) ? (key + 32) : (effL - 1);
            prefetch_l1(kbp + (size_t)kpf * Hn + hb);

            float4 k4[2];
            #pragma unroll
            for (int i = 0; i < 2; i++)
                k4[i] = *reinterpret_cast<const float4*>(&kbp[kc * Hn + hb + i * 4]);

            float sa0 = wsum_l, sb0 = 0.f, sa1 = wsum_l, sb1 = 0.f;
            #pragma unroll
            for (int i = 0; i < 2; i++) {
                // query row0
                float d0 = fminf(fmaf(qa[i].x, k4[i].x, 1.f), 1e18f);
                float d1 = fminf(fmaf(qa[i].y, k4[i].y, 1.f), 1e18f);
                float d2 = fminf(fmaf(qa[i].z, k4[i].z, 1.f), 1e18f);
                float d3 = fminf(fmaf(qa[i].w, k4[i].w, 1.f), 1e18f);
                float n01 = fmaf(w2[i].x, d1, w2[i].y * d0);
                float n23 = fmaf(w2[i].z, d3, w2[i].w * d2);
                float r01, r23;
                asm("rcp.approx.f32 %0, %1;" : "=f"(r01) : "f"(d0 * d1));
                asm("rcp.approx.f32 %0, %1;" : "=f"(r23) : "f"(d2 * d3));
                sa0 = fmaf(n01, r01, sa0);
                sb0 = fmaf(n23, r23, sb0);
                // query row1
                float e0 = fminf(fmaf(qb[i].x, k4[i].x, 1.f), 1e18f);
                float e1 = fminf(fmaf(qb[i].y, k4[i].y, 1.f), 1e18f);
                float e2 = fminf(fmaf(qb[i].z, k4[i].z, 1.f), 1e18f);
                float e3 = fminf(fmaf(qb[i].w, k4[i].w, 1.f), 1e18f);
                float m01 = fmaf(w2[i].x, e1, w2[i].y * e0);
                float m23 = fmaf(w2[i].z, e3, w2[i].w * e2);
                float u01, u23;
                asm("rcp.approx.f32 %0, %1;" : "=f"(u01) : "f"(e0 * e1));
                asm("rcp.approx.f32 %0, %1;" : "=f"(u23) : "f"(e2 * e3));
                sa1 = fmaf(m01, u01, sa1);
                sb1 = fmaf(m23, u23, sb1);
            }
            float s = sa0 + sb0;
            float t = sa1 + sb1;

            // reduce across the 16 lanes of each key group (both keys at once)
            s += __shfl_xor_sync(0xffffffffu, s, 1);
            t += __shfl_xor_sync(0xffffffffu, t, 1);
            s += __shfl_xor_sync(0xffffffffu, s, 2);
            t += __shfl_xor_sync(0xffffffffu, t, 2);
            s += __shfl_xor_sync(0xffffffffu, s, 4);
            t += __shfl_xor_sync(0xffffffffu, t, 4);
            s += __shfl_xor_sync(0xffffffffu, s, 8);
            t += __shfl_xor_sync(0xffffffffu, t, 8);

            if ((lane & 15) == 0 && key < effL) {
                s_sc[0][key] = s;
                s_sc[1][key] = t;
            }
        }
        __syncthreads();

        // ---- Pass 2a: per-row block max (writes s_rmax only) ----
        #pragma unroll
        for (int r = 0; r < 2; r++) {
            float m = -3.0e38f;
            for (int jj = tid; jj < effL; jj += 256) m = fmaxf(m, s_sc[r][jj]);
            #pragma unroll
            for (int o = 16; o > 0; o >>= 1)
                m = fmaxf(m, __shfl_xor_sync(0xffffffffu, m, o));
            if (lane == 0) s_rmax[r][warp] = m;
        }
        __syncthreads();

        // ---- Pass 2b: exp + sum (reads s_rmax, writes s_rsum: no aliasing) ----
        #pragma unroll
        for (int r = 0; r < 2; r++) {
            float M = s_rmax[r][0];
            #pragma unroll
            for (int k = 1; k < 8; k++) M = fmaxf(M, s_rmax[r][k]);

            float z = 0.f;
            for (int jj = tid; jj < effL; jj += 256) {
                const float e = __expf(s_sc[r][jj] - M);
                s_sc[r][jj] = e;
                z += e;
            }
            #pragma unroll
            for (int o = 16; o > 0; o >>= 1)
                z += __shfl_xor_sync(0xffffffffu, z, o);
            if (lane == 0) s_rsum[r][warp] = z;
        }
        __syncthreads();
        Z0 = s_rsum[0][0]; Z1 = s_rsum[1][0];
        #pragma unroll
        for (int k = 1; k < 8; k++) {
            Z0 += s_rsum[0][k];
            Z1 += s_rsum[1][k];
        }
    } else {
        // valid_len == 0: reference gives softmax over all -1e6 -> uniform
        for (int jj = tid; jj < KVn; jj += 256) {
            s_sc[0][jj] = 1.0f;
            s_sc[1][jj] = 1.0f;
        }
        __syncthreads();
        Z0 = (float)KVn;
        Z1 = (float)KVn;
    }

    // ---- Pass 3: AV with LDG.128 + prefetch ----
    const int c4   = (tid & 63) << 2;
    const int joff = tid >> 6;
    const float* vrow = values + (size_t)b * KVn * VSn + c4;

    float a0x = 0.f, a0y = 0.f, a0z = 0.f, a0w = 0.f;
    float a1x = 0.f, a1y = 0.f, a1z = 0.f, a1w = 0.f;
    #pragma unroll 4
    for (int j = joff; j < effL; j += 4) {
        const int jpf = (j + 32 < effL) ? (j + 32) : j;
        prefetch_l1(vrow + (size_t)jpf * VSn);
        const float4 v = *reinterpret_cast<const float4*>(vrow + (size_t)j * VSn);
        const float p0 = s_sc[0][j];
        const float p1 = s_sc[1][j];
        a0x = fmaf(p0, v.x, a0x);  a1x = fmaf(p1, v.x, a1x);
        a0y = fmaf(p0, v.y, a0y);  a1y = fmaf(p1, v.y, a1y);
        a0z = fmaf(p0, v.z, a0z);  a1z = fmaf(p1, v.z, a1z);
        a0w = fmaf(p0, v.w, a0w);  a1w = fmaf(p1, v.w, a1w);
    }
    *reinterpret_cast<float4*>(&s_av[0][joff][c4]) = make_float4(a0x, a0y, a0z, a0w);
    *reinterpret_cast<float4*>(&s_av[1][joff][c4]) = make_float4(a1x, a1y, a1z, a1w);
    __syncthreads();

    {
        const int c = tid;
        const float o0 = (s_av[0][0][c] + s_av[0][1][c]) +
                         (s_av[0][2][c] + s_av[0][3][c]);
        const float o1 = (s_av[1][0][c] + s_av[1][1][c]) +
                         (s_av[1][2][c] + s_av[1][3][c]);
        out[row0 * VSn + c] = o0 / Z0;
        out[row1 * VSn + c] = o1 / Z1;
    }
}

// ---------------------------------------------------------------------------
extern "C" void kernel_launch(void* const* d_in, const int* in_sizes, int n_in,
                              void* d_out, int out_size) {
    const float* queries = (const float*)d_in[0];
    const float* keys    = (const float*)d_in[1];
    const float* values  = (const float*)d_in[2];
    const int*   valid   = (const int*)d_in[3];
    const float* Wq      = (const float*)d_in[4];
    const float* Wk      = (const float*)d_in[5];
    const float* wv      = (const float*)d_in[6];
    float* out           = (float*)d_out;

    proj_kernel<<<(Bn * Qn + Bn * KVn) / 8, 512>>>(queries, keys, Wq, Wk, valid);
    attn_kernel<<<(Bn * Qn) / 2, 256>>>(values, valid, wv, out);
}

// round 16
// speedup vs baseline: 1.0419x; 1.0419x over previous
#include <cuda_runtime.h>
#include <cstdint>

// Problem dims (fixed by the reference)
#define Bn  4
#define Qn  256
#define KVn 1024
#define Hn  128
#define VSn 256
#define TK  32                  // keys per smem tile (16KB)

// Scratch (no cudaMalloc allowed)
__device__ float g_Eq[Bn * Qn * Hn];    // e^{2*clamp(q_proj)}
__device__ float g_Ek[Bn * KVn * Hn];   // e^{2*clamp(k_proj)}

// 2*log2(e): e^{2x} = 2^{x * 2*log2(e)}
#define TWO_LOG2E 2.885390081777927f

// ---------------------------------------------------------------------------
// Kernel 1: project rows, emit E = exp2(clamp(proj, +-40) * 2*log2(e)).
// 512 threads: thread = (4 output cols, 1 row, K-half). Split-K halves the
// FMA chain; halves combined via smem. W loaded as float4 (LDG.128).
// Key rows >= valid_len are skipped entirely (their bytes may be staged by
// cp.async downstream, but the resulting scores are discarded).
// ---------------------------------------------------------------------------
__global__ __launch_bounds__(512)
void proj_kernel(const float* __restrict__ queries,
                 const float* __restrict__ keys,
                 const float* __restrict__ Wq,
                 const float* __restrict__ Wk,
                 const int* __restrict__ valid_lens) {
    const int r0 = blockIdx.x * 8;
    const float* in;
    const float* W;
    float* outp;
    if (r0 < Bn * Qn) {
        in   = queries + r0 * Hn;
        W    = Wq;
        outp = g_Eq + r0 * Hn;
    } else {
        const int rr = r0 - Bn * Qn;          // global key row
        const int b  = rr >> 10;              // / KVn
        const int j0 = rr & (KVn - 1);
        if (j0 >= valid_lens[b]) return;      // scores there are never used
        in   = keys + rr * Hn;
        W    = Wk;
        outp = g_Ek + rr * Hn;
    }
    __shared__ float s[8][Hn];        // input rows
    __shared__ float part[8][Hn];     // K-half-1 partials

    const int t = threadIdx.x;
    #pragma unroll
    for (int u = 0; u < 2; u++) {
        const int idx = t + u * 512;
        s[idx >> 7][idx & 127] = in[idx];
    }
    __syncthreads();

    const int c4  = (t & 31) << 2;    // output column group (4 cols)
    const int row = (t >> 5) & 7;     // output row
    const int kh  = t >> 8;           // K half (0 or 1)

    const float* Wp   = W + kh * 64 * Hn + c4;
    const float* srow = &s[row][kh * 64];

    float ax = 0.f, ay = 0.f, az = 0.f, aw = 0.f;
    #pragma unroll 8
    for (int kk = 0; kk < 64; kk++) {
        const float  x = srow[kk];                       // warp-broadcast LDS
        const float4 w = *reinterpret_cast<const float4*>(Wp + kk * Hn);
        ax = fmaf(x, w.x, ax);
        ay = fmaf(x, w.y, ay);
        az = fmaf(x, w.z, az);
        aw = fmaf(x, w.w, aw);
    }

    if (kh == 1)
        *reinterpret_cast<float4*>(&part[row][c4]) = make_float4(ax, ay, az, aw);
    __syncthreads();
    if (kh == 0) {
        const float4 p = *reinterpret_cast<const float4*>(&part[row][c4]);
        float v[4] = {ax + p.x, ay + p.y, az + p.z, aw + p.w};
        float e[4];
        #pragma unroll
        for (int i = 0; i < 4; i++) {
            const float pc = fminf(fmaxf(v[i], -40.f), 40.f) * TWO_LOG2E;
            asm("ex2.approx.f32 %0, %1;" : "=f"(e[i]) : "f"(pc));
        }
        *reinterpret_cast<float4*>(&outp[row * Hn + c4]) =
            make_float4(e[0], e[1], e[2], e[3]);
    }
}

// ---------------------------------------------------------------------------
// Kernel 2 (fused): one block per query PAIR. 256 threads, 4 blocks/SM.
// Batch map b = (pair + (pair>>2)) & 3: bijective; blocks sharing an SM
// cycle through batches.
//
// Pass 1 (scores): K staged through smem with a double-buffered cp.async
//   pipeline (32-key / 16KB tiles). Bulk loads are issued cooperatively by
//   all 256 threads and overlap the previous tile's compute, so the per-key
//   dependent chain starts at LDS (~29 cyc) instead of L2 (~250-600 cyc).
//   16-lane-per-key geometry, 2 keys/warp, both queries per key.
//   tanh(x) = 1 - 2/(Eq*Ek + 1); Sum_h w_h hoisted.
//   MUFU halved by pairing: w0/d0 + w1/d1 = (w0*d1c + w1*d0c)*rcp(d0c*d1c),
//   d clamped at 1e18 (term < 3e-18 there -> exact-enough, finite products).
// Pass 2: per-row block softmax, race-free (separate max/sum scratch),
//   matching -1e6 masking; valid_len==0 -> uniform over all KV.
// Pass 3: AV with LDG.128 (independent loads, MLP-rich); partials in smem
//   UNION'd with the K tile buffers (phases are barrier-separated).
// ---------------------------------------------------------------------------
__global__ __launch_bounds__(256, 4)
void attn_kernel(const float* __restrict__ values,
                 const int* __restrict__ valid_lens,
                 const float* __restrict__ wv,
                 float* __restrict__ out) {
    const int pair = blockIdx.x;                 // [0, 512)
    const int qp   = pair >> 2;                  // [0, 128)
    const int b    = (pair + qp) & 3;            // SM-cycling batch mix
    const int row0 = (b << 8) + (qp << 1);
    const int row1 = row0 + 1;
    const int tid  = threadIdx.x;
    const int lane = tid & 31;
    const int warp = tid >> 5;

    __shared__ float s_sc[2][KVn];
    __shared__ __align__(16) union U {
        float kt[2][TK][Hn];     // pass 1: double-buffered K tiles (32KB)
        float av[2][4][VSn];     // pass 3: AV partials (8KB)
    } u;
    __shared__ float s_rmax[2][8];
    __shared__ float s_rsum[2][8];

    const int L     = valid_lens[b];
    const bool uni  = (L <= 0);
    const int effL  = uni ? KVn : L;

    float Z0, Z1;
    if (!uni) {
        // ---- Pass 1: scores for both query rows ----
        const int sub = lane >> 4;          // which key of the duo (0..1)
        const int hb  = (lane & 15) << 3;   // h-chunk base (8 floats)

        float4 qa[2], qb[2], w2[2];
        float wsum_l = 0.f;
        #pragma unroll
        for (int i = 0; i < 2; i++) {
            qa[i] = *reinterpret_cast<const float4*>(&g_Eq[row0 * Hn + hb + i * 4]);
            qb[i] = *reinterpret_cast<const float4*>(&g_Eq[row1 * Hn + hb + i * 4]);
            float4 w = *reinterpret_cast<const float4*>(&wv[hb + i * 4]);
            wsum_l += ((w.x + w.y) + (w.z + w.w));
            w2[i] = make_float4(-2.f * w.x, -2.f * w.y, -2.f * w.z, -2.f * w.w);
        }
        const float* kbp = g_Ek + (size_t)b * KVn * Hn;
        const int nT = (effL + TK - 1) / TK;   // tiles always inside g_Ek

        // cooperative async tile load: 256 threads x 4 x 16B = 16KB
        const unsigned int kt0 =
            (unsigned int)__cvta_generic_to_shared(&u.kt[0][0][0]);
        const unsigned int kt1 =
            (unsigned int)__cvta_generic_to_shared(&u.kt[1][0][0]);

        #define LOAD_TILE(tt, dstbase)                                        \
            do {                                                              \
                const char* _src = (const char*)(kbp + (size_t)(tt) * TK * Hn); \
                _Pragma("unroll")                                             \
                for (int _k = 0; _k < 4; _k++) {                              \
                    const int _off = tid * 16 + _k * 4096;                    \
                    asm volatile("cp.async.cg.shared.global [%0], [%1], 16;"  \
                                 :: "r"((dstbase) + _off), "l"(_src + _off)); \
                }                                                             \
                asm volatile("cp.async.commit_group;");                       \
            } while (0)

        LOAD_TILE(0, kt0);
        for (int tt = 0; tt < nT; tt++) {
            const int bb = tt & 1;
            if (tt + 1 < nT) {
                LOAD_TILE(tt + 1, bb ? kt0 : kt1);
                asm volatile("cp.async.wait_group 1;");
            } else {
                asm volatile("cp.async.wait_group 0;");
            }
            __syncthreads();   // tile bb visible to all threads

            const int base = tt * TK;
            #pragma unroll
            for (int it = 0; it < 2; it++) {
                const int kl  = it * 16 + warp * 2 + sub;   // local key 0..31
                const int key = base + kl;

                float4 k4[2];
                #pragma unroll
                for (int i = 0; i < 2; i++)
                    k4[i] = *reinterpret_cast<const float4*>(&u.kt[bb][kl][hb + i * 4]);

                float sa0 = wsum_l, sb0 = 0.f, sa1 = wsum_l, sb1 = 0.f;
                #pragma unroll
                for (int i = 0; i < 2; i++) {
                    // query row0
                    float d0 = fminf(fmaf(qa[i].x, k4[i].x, 1.f), 1e18f);
                    float d1 = fminf(fmaf(qa[i].y, k4[i].y, 1.f), 1e18f);
                    float d2 = fminf(fmaf(qa[i].z, k4[i].z, 1.f), 1e18f);
                    float d3 = fminf(fmaf(qa[i].w, k4[i].w, 1.f), 1e18f);
                    float n01 = fmaf(w2[i].x, d1, w2[i].y * d0);
                    float n23 = fmaf(w2[i].z, d3, w2[i].w * d2);
                    float r01, r23;
                    asm("rcp.approx.f32 %0, %1;" : "=f"(r01) : "f"(d0 * d1));
                    asm("rcp.approx.f32 %0, %1;" : "=f"(r23) : "f"(d2 * d3));
                    sa0 = fmaf(n01, r01, sa0);
                    sb0 = fmaf(n23, r23, sb0);
                    // query row1
                    float e0 = fminf(fmaf(qb[i].x, k4[i].x, 1.f), 1e18f);
                    float e1 = fminf(fmaf(qb[i].y, k4[i].y, 1.f), 1e18f);
                    float e2 = fminf(fmaf(qb[i].z, k4[i].z, 1.f), 1e18f);
                    float e3 = fminf(fmaf(qb[i].w, k4[i].w, 1.f), 1e18f);
                    float m01 = fmaf(w2[i].x, e1, w2[i].y * e0);
                    float m23 = fmaf(w2[i].z, e3, w2[i].w * e2);
                    float u01, u23;
                    asm("rcp.approx.f32 %0, %1;" : "=f"(u01) : "f"(e0 * e1));
                    asm("rcp.approx.f32 %0, %1;" : "=f"(u23) : "f"(e2 * e3));
                    sa1 = fmaf(m01, u01, sa1);
                    sb1 = fmaf(m23, u23, sb1);
                }
                float s = sa0 + sb0;
                float t = sa1 + sb1;

                // reduce across the 16 lanes of each key group
                s += __shfl_xor_sync(0xffffffffu, s, 1);
                t += __shfl_xor_sync(0xffffffffu, t, 1);
                s += __shfl_xor_sync(0xffffffffu, s, 2);
                t += __shfl_xor_sync(0xffffffffu, t, 2);
                s += __shfl_xor_sync(0xffffffffu, s, 4);
                t += __shfl_xor_sync(0xffffffffu, t, 4);
                s += __shfl_xor_sync(0xffffffffu, s, 8);
                t += __shfl_xor_sync(0xffffffffu, t, 8);

                if ((lane & 15) == 0 && key < effL) {
                    s_sc[0][key] = s;
                    s_sc[1][key] = t;
                }
            }
            __syncthreads();   // all reads of buf bb done before tt+2 loads it
        }
        #undef LOAD_TILE

        // ---- Pass 2a: per-row block max (writes s_rmax only) ----
        #pragma unroll
        for (int r = 0; r < 2; r++) {
            float m = -3.0e38f;
            for (int jj = tid; jj < effL; jj += 256) m = fmaxf(m, s_sc[r][jj]);
            #pragma unroll
            for (int o = 16; o > 0; o >>= 1)
                m = fmaxf(m, __shfl_xor_sync(0xffffffffu, m, o));
            if (lane == 0) s_rmax[r][warp] = m;
        }
        __syncthreads();

        // ---- Pass 2b: exp + sum (reads s_rmax, writes s_rsum) ----
        #pragma unroll
        for (int r = 0; r < 2; r++) {
            float M = s_rmax[r][0];
            #pragma unroll
            for (int k = 1; k < 8; k++) M = fmaxf(M, s_rmax[r][k]);

            float z = 0.f;
            for (int jj = tid; jj < effL; jj += 256) {
                const float e = __expf(s_sc[r][jj] - M);
                s_sc[r][jj] = e;
                z += e;
            }
            #pragma unroll
            for (int o = 16; o > 0; o >>= 1)
                z += __shfl_xor_sync(0xffffffffu, z, o);
            if (lane == 0) s_rsum[r][warp] = z;
        }
        __syncthreads();
        Z0 = s_rsum[0][0]; Z1 = s_rsum[1][0];
        #pragma unroll
        for (int k = 1; k < 8; k++) {
            Z0 += s_rsum[0][k];
            Z1 += s_rsum[1][k];
        }
    } else {
        // valid_len == 0: reference gives softmax over all -1e6 -> uniform
        for (int jj = tid; jj < KVn; jj += 256) {
            s_sc[0][jj] = 1.0f;
            s_sc[1][jj] = 1.0f;
        }
        __syncthreads();
        Z0 = (float)KVn;
        Z1 = (float)KVn;
    }

    // ---- Pass 3: AV with LDG.128 (u.kt no longer read; reuse as u.av) ----
    const int c4   = (tid & 63) << 2;
    const int joff = tid >> 6;
    const float* vrow = values + (size_t)b * KVn * VSn + c4;

    float a0x = 0.f, a0y = 0.f, a0z = 0.f, a0w = 0.f;
    float a1x = 0.f, a1y = 0.f, a1z = 0.f, a1w = 0.f;
    #pragma unroll 4
    for (int j = joff; j < effL; j += 4) {
        const float4 v = *reinterpret_cast<const float4*>(vrow + (size_t)j * VSn);
        const float p0 = s_sc[0][j];
        const float p1 = s_sc[1][j];
        a0x = fmaf(p0, v.x, a0x);  a1x = fmaf(p1, v.x, a1x);
        a0y = fmaf(p0, v.y, a0y);  a1y = fmaf(p1, v.y, a1y);
        a0z = fmaf(p0, v.z, a0z);  a1z = fmaf(p1, v.z, a1z);
        a0w = fmaf(p0, v.w, a0w);  a1w = fmaf(p1, v.w, a1w);
    }
    __syncthreads();   // pass-1/2 uses of the union are done in all warps
    *reinterpret_cast<float4*>(&u.av[0][joff][c4]) = make_float4(a0x, a0y, a0z, a0w);
    *reinterpret_cast<float4*>(&u.av[1][joff][c4]) = make_float4(a1x, a1y, a1z, a1w);
    __syncthreads();

    {
        const int c = tid;
        const float o0 = (u.av[0][0][c] + u.av[0][1][c]) +
                         (u.av[0][2][c] + u.av[0][3][c]);
        const float o1 = (u.av[1][0][c] + u.av[1][1][c]) +
                         (u.av[1][2][c] + u.av[1][3][c]);
        out[row0 * VSn + c] = o0 / Z0;
        out[row1 * VSn + c] = o1 / Z1;
    }
}

// ---------------------------------------------------------------------------
extern "C" void kernel_launch(void* const* d_in, const int* in_sizes, int n_in,
                              void* d_out, int out_size) {
    const float* queries = (const float*)d_in[0];
    const float* keys    = (const float*)d_in[1];
    const float* values  = (const float*)d_in[2];
    const int*   valid   = (const int*)d_in[3];
    const float* Wq      = (const float*)d_in[4];
    const float* Wk      = (const float*)d_in[5];
    const float* wv      = (const float*)d_in[6];
    float* out           = (float*)d_out;

    proj_kernel<<<(Bn * Qn + Bn * KVn) / 8, 512>>>(queries, keys, Wq, Wk, valid);
    attn_kernel<<<(Bn * Qn) / 2, 256>>>(values, valid, wv, out);
}

// round 17
// speedup vs baseline: 1.1635x; 1.1167x over previous
#include <cuda_runtime.h>
#include <cstdint>

// Problem dims (fixed by the reference)
#define Bn  4
#define Qn  256
#define KVn 1024
#define Hn  128
#define VSn 256

// Scratch (no cudaMalloc allowed)
__device__ float g_Eq[Bn * Qn * Hn];    // e^{2*clamp(q_proj)}
__device__ float g_Ek[Bn * KVn * Hn];   // e^{2*clamp(k_proj)}

// 2*log2(e): e^{2x} = 2^{x * 2*log2(e)}
#define TWO_LOG2E 2.885390081777927f

// ---------------------------------------------------------------------------
// Kernel 1: project rows, emit E = exp2(clamp(proj, +-40) * 2*log2(e)).
// 512 threads: thread = (4 output cols, 1 row, K-half). Split-K halves the
// FMA chain; halves combined via smem. W loaded as float4 (LDG.128).
// Key rows >= valid_len are skipped entirely (never read downstream).
// ---------------------------------------------------------------------------
__global__ __launch_bounds__(512)
void proj_kernel(const float* __restrict__ queries,
                 const float* __restrict__ keys,
                 const float* __restrict__ Wq,
                 const float* __restrict__ Wk,
                 const int* __restrict__ valid_lens) {
    const int r0 = blockIdx.x * 8;
    const float* in;
    const float* W;
    float* outp;
    if (r0 < Bn * Qn) {
        in   = queries + r0 * Hn;
        W    = Wq;
        outp = g_Eq + r0 * Hn;
    } else {
        const int rr = r0 - Bn * Qn;          // global key row
        const int b  = rr >> 10;              // / KVn
        const int j0 = rr & (KVn - 1);
        if (j0 >= valid_lens[b]) return;      // these Ek rows are never read
        in   = keys + rr * Hn;
        W    = Wk;
        outp = g_Ek + rr * Hn;
    }
    __shared__ float s[8][Hn];        // input rows
    __shared__ float part[8][Hn];     // K-half-1 partials

    const int t = threadIdx.x;
    #pragma unroll
    for (int u = 0; u < 2; u++) {
        const int idx = t + u * 512;
        s[idx >> 7][idx & 127] = in[idx];
    }
    __syncthreads();

    const int c4  = (t & 31) << 2;    // output column group (4 cols)
    const int row = (t >> 5) & 7;     // output row
    const int kh  = t >> 8;           // K half (0 or 1)

    const float* Wp   = W + kh * 64 * Hn + c4;
    const float* srow = &s[row][kh * 64];

    float ax = 0.f, ay = 0.f, az = 0.f, aw = 0.f;
    #pragma unroll 8
    for (int kk = 0; kk < 64; kk++) {
        const float  x = srow[kk];                       // warp-broadcast LDS
        const float4 w = *reinterpret_cast<const float4*>(Wp + kk * Hn);
        ax = fmaf(x, w.x, ax);
        ay = fmaf(x, w.y, ay);
        az = fmaf(x, w.z, az);
        aw = fmaf(x, w.w, aw);
    }

    if (kh == 1)
        *reinterpret_cast<float4*>(&part[row][c4]) = make_float4(ax, ay, az, aw);
    __syncthreads();
    if (kh == 0) {
        const float4 p = *reinterpret_cast<const float4*>(&part[row][c4]);
        float v[4] = {ax + p.x, ay + p.y, az + p.z, aw + p.w};
        float e[4];
        #pragma unroll
        for (int i = 0; i < 4; i++) {
            const float pc = fminf(fmaxf(v[i], -40.f), 40.f) * TWO_LOG2E;
            asm("ex2.approx.f32 %0, %1;" : "=f"(e[i]) : "f"(pc));
        }
        *reinterpret_cast<float4*>(&outp[row * Hn + c4]) =
            make_float4(e[0], e[1], e[2], e[3]);
    }
}

// ---------------------------------------------------------------------------
// Kernel 2 (fused): one block per query ROW. grid 1024, 256 threads,
// __launch_bounds__(256, 6) -> regs <= 42 -> 6 blocks/SM = 48 warps/SM.
// (R=2 reuse was abandoned: at grid 512 it pinned the SM to 3.46 blocks and
// the kernel was warp-starved, not L1-bound.)
// Batch map: qi = bid>>2, b = (bid+qi)&3 (bijective), so blocks sharing an
// SM cycle through batches with unequal valid_lens.
//
// Pass 1 (scores): 16-lane-per-key, 2 keys/warp, plain LDG.128 from g_Ek.
//   tanh(x) = 1 - 2/(Eq*Ek + 1); Sum_h w_h hoisted into accumulator init.
//   MUFU halved by pairing: w0/d0 + w1/d1 = (w0*d1c + w1*d0c)*rcp(d0c*d1c),
//   d clamped at 1e18 (true term < 3e-18 there -> clamp exact-enough, all
//   products finite -> no inf*0).
// Pass 2: block softmax, race-free (separate max/sum scratch), matching the
//   -1e6 masking semantics; valid_len==0 -> uniform over all KV.
// Pass 3: AV with LDG.128: thread owns 4 columns and one of 4 j-residues;
//   partials combined through smem.
// ---------------------------------------------------------------------------
__global__ __launch_bounds__(256, 6)
void attn_kernel(const float* __restrict__ values,
                 const int* __restrict__ valid_lens,
                 const float* __restrict__ wv,
                 float* __restrict__ out) {
    const int bid  = blockIdx.x;                 // [0, 1024)
    const int qi   = bid >> 2;                   // [0, 256)
    const int b    = (bid + qi) & 3;             // SM-cycling batch mix
    const int row  = (b << 8) + qi;
    const int tid  = threadIdx.x;
    const int lane = tid & 31;
    const int warp = tid >> 5;

    __shared__ float s_sc[KVn];
    __shared__ float s_av[4][VSn];
    __shared__ float s_rmax[8];
    __shared__ float s_rsum[8];

    const int L     = valid_lens[b];
    const bool uni  = (L <= 0);
    const int effL  = uni ? KVn : L;

    float Z;
    if (!uni) {
        // ---- Pass 1: scores ----
        const int sub = lane >> 4;          // which key of the duo (0..1)
        const int hb  = (lane & 15) << 3;   // h-chunk base (8 floats)

        float4 qa[2], w2[2];
        float wsum_l = 0.f;
        #pragma unroll
        for (int i = 0; i < 2; i++) {
            qa[i] = *reinterpret_cast<const float4*>(&g_Eq[row * Hn + hb + i * 4]);
            float4 w = *reinterpret_cast<const float4*>(&wv[hb + i * 4]);
            wsum_l += ((w.x + w.y) + (w.z + w.w));
            w2[i] = make_float4(-2.f * w.x, -2.f * w.y, -2.f * w.z, -2.f * w.w);
        }
        const float* kbp = g_Ek + b * (KVn * Hn);

        for (int j0 = warp * 2; j0 < effL; j0 += 16) {
            const int key = j0 + sub;
            const int kc  = (key < effL) ? key : (effL - 1);   // safe load

            float4 k4[2];
            #pragma unroll
            for (int i = 0; i < 2; i++)
                k4[i] = *reinterpret_cast<const float4*>(&kbp[kc * Hn + hb + i * 4]);

            float sa = wsum_l, sb = 0.f;
            #pragma unroll
            for (int i = 0; i < 2; i++) {
                float d0 = fminf(fmaf(qa[i].x, k4[i].x, 1.f), 1e18f);
                float d1 = fminf(fmaf(qa[i].y, k4[i].y, 1.f), 1e18f);
                float d2 = fminf(fmaf(qa[i].z, k4[i].z, 1.f), 1e18f);
                float d3 = fminf(fmaf(qa[i].w, k4[i].w, 1.f), 1e18f);
                float n01 = fmaf(w2[i].x, d1, w2[i].y * d0);
                float n23 = fmaf(w2[i].z, d3, w2[i].w * d2);
                float r01, r23;
                asm("rcp.approx.f32 %0, %1;" : "=f"(r01) : "f"(d0 * d1));
                asm("rcp.approx.f32 %0, %1;" : "=f"(r23) : "f"(d2 * d3));
                sa = fmaf(n01, r01, sa);
                sb = fmaf(n23, r23, sb);
            }
            float s = sa + sb;

            // reduce across the 16 lanes of each key group (both keys at once)
            s += __shfl_xor_sync(0xffffffffu, s, 1);
            s += __shfl_xor_sync(0xffffffffu, s, 2);
            s += __shfl_xor_sync(0xffffffffu, s, 4);
            s += __shfl_xor_sync(0xffffffffu, s, 8);

            if ((lane & 15) == 0 && key < effL) s_sc[key] = s;
        }
        __syncthreads();

        // ---- Pass 2a: block max (writes s_rmax only) ----
        float m = -3.0e38f;
        for (int jj = tid; jj < effL; jj += 256) m = fmaxf(m, s_sc[jj]);
        #pragma unroll
        for (int o = 16; o > 0; o >>= 1)
            m = fmaxf(m, __shfl_xor_sync(0xffffffffu, m, o));
        if (lane == 0) s_rmax[warp] = m;
        __syncthreads();

        // ---- Pass 2b: exp + sum (reads s_rmax, writes s_rsum) ----
        float M = s_rmax[0];
        #pragma unroll
        for (int k = 1; k < 8; k++) M = fmaxf(M, s_rmax[k]);

        float z = 0.f;
        for (int jj = tid; jj < effL; jj += 256) {
            const float e = __expf(s_sc[jj] - M);
            s_sc[jj] = e;
            z += e;
        }
        #pragma unroll
        for (int o = 16; o > 0; o >>= 1)
            z += __shfl_xor_sync(0xffffffffu, z, o);
        if (lane == 0) s_rsum[warp] = z;
        __syncthreads();
        Z = s_rsum[0];
        #pragma unroll
        for (int k = 1; k < 8; k++) Z += s_rsum[k];
    } else {
        // valid_len == 0: reference gives softmax over all -1e6 -> uniform
        for (int jj = tid; jj < KVn; jj += 256) s_sc[jj] = 1.0f;
        __syncthreads();
        Z = (float)KVn;
    }

    // ---- Pass 3: AV with LDG.128 ----
    const int c4   = (tid & 63) << 2;
    const int joff = tid >> 6;
    const float* vrow = values + b * (KVn * VSn) + c4;

    float ax = 0.f, ay = 0.f, az = 0.f, aw = 0.f;
    #pragma unroll 4
    for (int j = joff; j < effL; j += 4) {
        const float4 v = *reinterpret_cast<const float4*>(vrow + j * VSn);
        const float p = s_sc[j];
        ax = fmaf(p, v.x, ax);
        ay = fmaf(p, v.y, ay);
        az = fmaf(p, v.z, az);
        aw = fmaf(p, v.w, aw);
    }
    *reinterpret_cast<float4*>(&s_av[joff][c4]) = make_float4(ax, ay, az, aw);
    __syncthreads();

    {
        const int c = tid;
        const float o0 = (s_av[0][c] + s_av[1][c]) + (s_av[2][c] + s_av[3][c]);
        out[row * VSn + c] = o0 / Z;
    }
}

// ---------------------------------------------------------------------------
extern "C" void kernel_launch(void* const* d_in, const int* in_sizes, int n_in,
                              void* d_out, int out_size) {
    const float* queries = (const float*)d_in[0];
    const float* keys    = (const float*)d_in[1];
    const float* values  = (const float*)d_in[2];
    const int*   valid   = (const int*)d_in[3];
    const float* Wq      = (const float*)d_in[4];
    const float* Wk      = (const float*)d_in[5];
    const float* wv      = (const float*)d_in[6];
    float* out           = (float*)d_out;

    proj_kernel<<<(Bn * Qn + Bn * KVn) / 8, 512>>>(queries, keys, Wq, Wk, valid);
    attn_kernel<<<Bn * Qn, 256>>>(values, valid, wv, out);
}